// round 15
// baseline (speedup 1.0000x reference)
#include <cuda_runtime.h>
#include <cuda_fp16.h>
#include <math.h>
#include <stdint.h>

#define NN 1024
#define DD 512
#define HH 16
#define DH 32
#define NBINS 68

// ---- scratch layout (float offsets into one big __device__ buffer) ----
#define OFF_HN     0
#define OFF_Q      524288
#define OFF_K      1048576
#define OFF_V      1572864
#define OFF_G      2097152
#define OFF_EK     2621440          /* E = exp(logK) fp16: 16M halves = 8M floats */
#define OFF_EU     11010048         /* exp(log_u), 16*1024 */
#define OFF_EV     11026432         /* exp(log_v), 16*1024 */
#define OFF_LOGMU  19398656
#define OFF_LOGNU  19415040
#define OFF_U      19431424
#define OFF_V2     19447808
#define OFF_VXP    19464192
#define OFF_ATTN   20037632
#define OFF_XC     20561920
#define OFF_HMID   20611072
#define OFF_H2     21135360
#define OFF_FFA    21659648
#define OFF_FFB    23756800
#define OFF_FFG    25853952
#define BUF_TOTAL  27951104

__device__ float g_buf[BUF_TOTAL];

// Output layout: [h | x_res | log_u | log_v]
#define OUT_H 0
#define OUT_X 524288
#define OUT_U 527360
#define OUT_V 543744

// ---------------------------------------------------------------------------
__device__ __forceinline__ float tf32r(float x) {
    uint32_t u;
    asm("cvt.rna.tf32.f32 %0, %1;" : "=r"(u) : "f"(x));
    return __uint_as_float(u);
}

__device__ __forceinline__ uint32_t tf32u(float x) {
    uint32_t u;
    asm("cvt.rna.tf32.f32 %0, %1;" : "=r"(u) : "f"(x));
    return u;
}

__device__ __forceinline__ void mma_tf32(float* d, const uint32_t* a, const uint32_t* b) {
    asm volatile(
        "mma.sync.aligned.m16n8k8.row.col.f32.tf32.tf32.f32 "
        "{%0,%1,%2,%3}, {%4,%5,%6,%7}, {%8,%9}, {%0,%1,%2,%3};"
        : "+f"(d[0]), "+f"(d[1]), "+f"(d[2]), "+f"(d[3])
        : "r"(a[0]), "r"(a[1]), "r"(a[2]), "r"(a[3]), "r"(b[0]), "r"(b[1]));
}

#define CP_ASYNC16(smem_u32, gptr) \
    asm volatile("cp.async.cg.shared.global [%0], [%1], 16;" :: "r"(smem_u32), "l"(gptr))
#define CP_COMMIT() asm volatile("cp.async.commit_group;")
#define CP_WAIT(n)  asm volatile("cp.async.wait_group %0;" :: "n"(n))

// ---------------------------------------------------------------------------
// LayerNorm over last dim D=512. One block per row, 256 threads.
__global__ void ln_kernel(const float* __restrict__ inExt, int inOff,
                          const float* __restrict__ w, const float* __restrict__ b,
                          int outOff) {
    const float* in = inExt ? inExt : (g_buf + inOff);
    int row = blockIdx.x, tid = threadIdx.x;
    __shared__ float red[256];
    float x0 = in[row * DD + tid];
    float x1 = in[row * DD + 256 + tid];
    red[tid] = x0 + x1;
    __syncthreads();
    for (int o = 128; o; o >>= 1) { if (tid < o) red[tid] += red[tid + o]; __syncthreads(); }
    float m = red[0] * (1.0f / DD);
    __syncthreads();
    float d0 = x0 - m, d1 = x1 - m;
    red[tid] = d0 * d0 + d1 * d1;
    __syncthreads();
    for (int o = 128; o; o >>= 1) { if (tid < o) red[tid] += red[tid + o]; __syncthreads(); }
    float var = red[0] * (1.0f / DD);
    float rs = rsqrtf(var + 1e-5f);
    float* out = g_buf + outOff;
    out[row * DD + tid]       = d0 * rs * w[tid]       + b[tid];
    out[row * DD + 256 + tid] = d1 * rs * w[tid + 256] + b[tid + 256];
}

// ---------------------------------------------------------------------------
// TF32 tensor-core GEMM, double-buffered cp.async pipeline.
template<int BM, int BN>
__global__ void __launch_bounds__(256) tgemm_kernel(
    int aOff, const float* __restrict__ B0, const float* __restrict__ B1,
    const float* __restrict__ B2, const float* __restrict__ B3,
    int nPerW, int cOff, float* __restrict__ outExt,
    const float* __restrict__ resExt, int resOff,
    const float* __restrict__ mask, int M, int K) {
    constexpr int BK = 16;
    constexpr int WM = BM / 2, WN = BN / 4;
    constexpr int MT = WM / 16, NT = WN / 8;
    __shared__ float As[2][BM][BK + 4];
    __shared__ float Bs[2][BN][BK + 4];
    const float* A = g_buf + aOff;
    int m0 = blockIdx.y * BM, n0 = blockIdx.x * BN;
    int widx = n0 / nPerW;
    const float* Bw = (widx == 0) ? B0 : (widx == 1) ? B1 : (widx == 2) ? B2 : B3;
    int nloc0 = n0 - widx * nPerW;

    int tid = threadIdx.x, lane = tid & 31, wid = tid >> 5;
    int warpM = wid >> 2, warpN = wid & 3;

    int rA = tid >> 2, kqA = (tid & 3) << 2;

    float d[MT][NT][4];
#pragma unroll
    for (int mt = 0; mt < MT; ++mt)
#pragma unroll
        for (int nt = 0; nt < NT; ++nt)
#pragma unroll
            for (int q = 0; q < 4; ++q) d[mt][nt][q] = 0.0f;

    const int KT = K / BK;

    {
#pragma unroll
        for (int t0 = 0; t0 < BM * 4; t0 += 256) {
            int r = rA + (t0 >> 2);
            uint32_t sa = (uint32_t)__cvta_generic_to_shared(&As[0][r][kqA]);
            CP_ASYNC16(sa, &A[(m0 + r) * K + kqA]);
        }
#pragma unroll
        for (int t0 = 0; t0 < BN * 4; t0 += 256) {
            int r = rA + (t0 >> 2);
            uint32_t sa = (uint32_t)__cvta_generic_to_shared(&Bs[0][r][kqA]);
            CP_ASYNC16(sa, &Bw[(nloc0 + r) * K + kqA]);
        }
        CP_COMMIT();
    }

    for (int kt = 0; kt < KT; ++kt) {
        int st = kt & 1;
        if (kt + 1 < KT) {
            int k0n = (kt + 1) * BK;
            int sn = st ^ 1;
#pragma unroll
            for (int t0 = 0; t0 < BM * 4; t0 += 256) {
                int r = rA + (t0 >> 2);
                uint32_t sa = (uint32_t)__cvta_generic_to_shared(&As[sn][r][kqA]);
                CP_ASYNC16(sa, &A[(m0 + r) * K + k0n + kqA]);
            }
#pragma unroll
            for (int t0 = 0; t0 < BN * 4; t0 += 256) {
                int r = rA + (t0 >> 2);
                uint32_t sa = (uint32_t)__cvta_generic_to_shared(&Bs[sn][r][kqA]);
                CP_ASYNC16(sa, &Bw[(nloc0 + r) * K + k0n + kqA]);
            }
            CP_COMMIT();
            CP_WAIT(1);
        } else {
            CP_WAIT(0);
        }
        __syncthreads();
#pragma unroll
        for (int ks = 0; ks < 2; ++ks) {
            int kb = ks * 8;
            uint32_t a[MT][4], b[NT][2];
#pragma unroll
            for (int mt = 0; mt < MT; ++mt) {
                int r = warpM * WM + mt * 16 + (lane >> 2);
                int c = kb + (lane & 3);
                a[mt][0] = tf32u(As[st][r][c]);
                a[mt][1] = tf32u(As[st][r + 8][c]);
                a[mt][2] = tf32u(As[st][r][c + 4]);
                a[mt][3] = tf32u(As[st][r + 8][c + 4]);
            }
#pragma unroll
            for (int nt = 0; nt < NT; ++nt) {
                int r = warpN * WN + nt * 8 + (lane >> 2);
                int c = kb + (lane & 3);
                b[nt][0] = tf32u(Bs[st][r][c]);
                b[nt][1] = tf32u(Bs[st][r][c + 4]);
            }
#pragma unroll
            for (int mt = 0; mt < MT; ++mt)
#pragma unroll
                for (int nt = 0; nt < NT; ++nt) mma_tf32(d[mt][nt], a[mt], b[nt]);
        }
        __syncthreads();
    }

    float* outp = (outExt ? outExt : (g_buf + cOff)) + (long)widx * M * nPerW;
    const float* resp = resExt ? resExt : (resOff >= 0 ? (g_buf + resOff) : (const float*)0);
#pragma unroll
    for (int mt = 0; mt < MT; ++mt) {
        int row0 = m0 + warpM * WM + mt * 16 + (lane >> 2);
#pragma unroll
        for (int nt = 0; nt < NT; ++nt) {
            int col = nloc0 + warpN * WN + nt * 8 + (lane & 3) * 2;
#pragma unroll
            for (int half = 0; half < 2; ++half) {
                int row = row0 + half * 8;
                float2 v = make_float2(d[mt][nt][half * 2], d[mt][nt][half * 2 + 1]);
                if (resp) {
                    float mk = mask ? mask[row] : 1.0f;
                    float2 r2 = *(const float2*)&resp[row * nPerW + col];
                    v.x = r2.x + v.x * mk;
                    v.y = r2.y + v.y * mk;
                }
                *(float2*)&outp[row * nPerW + col] = v;
            }
        }
    }
}

// ---------------------------------------------------------------------------
// Per-head plain LN over DH=32; grid (2048, 2): y=0 -> Q, y=1 -> K.
__global__ void headln_kernel(int off0) {
    int off = off0 + (int)blockIdx.y * (NN * DD);
    int gid = blockIdx.x * 8 + (threadIdx.x >> 5);
    int lane = threadIdx.x & 31;
    int i = gid >> 4, h = gid & 15;
    float* p = g_buf + off + i * DD + h * DH + lane;
    float x = *p;
    float s = x;
#pragma unroll
    for (int o = 16; o; o >>= 1) s += __shfl_xor_sync(0xffffffffu, s, o);
    float m = s * (1.0f / DH);
    float d = x - m;
    float v = d * d;
#pragma unroll
    for (int o = 16; o; o >>= 1) v += __shfl_xor_sync(0xffffffffu, v, o);
    float var = v * (1.0f / DH);
    *p = d * rsqrtf(var + 1e-5f);
}

// ---------------------------------------------------------------------------
// E[h,i,j] = exp(pair_mask ? (QK/sqrt32 + bias - wd*d2/100)/eps : -1e9) [fp16]
// Full logit (minus bias) computed on tensor cores via augmented K=40:
//   cols 0-31 : Q*(s32*ie)  x  K
//   cols 32-34: xi*cs       x  xj*cs          (cs^2 = 0.02*wd*ie -> +0.02*wd*ie*xi.xj)
//   col  35   : -0.01*wd*ie*|xi|^2  x  1
//   col  36   : 1            x  -0.01*wd*ie*|xj|^2
//   cols 37-39: 0
__global__ void __launch_bounds__(256) logk_kernel(
    const int* __restrict__ bins, const float* __restrict__ pw,
    const float* __restrict__ wdl, const float* __restrict__ eps,
    const float* __restrict__ mask, const float* __restrict__ xr) {
    __shared__ float Qs[64][44], Ks[64][44];
    __shared__ float mi[64], mj[64], pwie[NBINS];
    __half* EK = (__half*)(g_buf + OFF_EK);
    int h = blockIdx.z, i0 = blockIdx.y * 64, j0 = blockIdx.x * 64;
    int tid = threadIdx.x, lane = tid & 31, wid = tid >> 5;
    int warpM = wid >> 2, warpN = wid & 3;

    float wd = 1.0f / (1.0f + expf(-wdl[h]));
    float ie = 1.0f / eps[h];
    const float s32 = 0.17677669529663687f;  // 1/sqrt(32)
    float qscale = s32 * ie;
    float cs = sqrtf(0.02f * wd * ie);
    float dcoef = -0.01f * wd * ie;

    // stage Q,K rows: cols 0..31 (Q pre-scaled by s32*ie), tf32-rounded
    for (int t = tid; t < 512; t += 256) {
        int r = t >> 3, kq = (t & 7) << 2;
        float4 q4 = *(const float4*)&g_buf[OFF_Q + (i0 + r) * DD + h * DH + kq];
        float4 k4 = *(const float4*)&g_buf[OFF_K + (j0 + r) * DD + h * DH + kq];
        Qs[r][kq + 0] = tf32r(q4.x * qscale); Qs[r][kq + 1] = tf32r(q4.y * qscale);
        Qs[r][kq + 2] = tf32r(q4.z * qscale); Qs[r][kq + 3] = tf32r(q4.w * qscale);
        Ks[r][kq + 0] = tf32r(k4.x); Ks[r][kq + 1] = tf32r(k4.y);
        Ks[r][kq + 2] = tf32r(k4.z); Ks[r][kq + 3] = tf32r(k4.w);
    }
    if (tid < 64) {
        int r = tid;
        float a0 = xr[(i0 + r) * 3 + 0], a1 = xr[(i0 + r) * 3 + 1], a2 = xr[(i0 + r) * 3 + 2];
        float b0 = xr[(j0 + r) * 3 + 0], b1 = xr[(j0 + r) * 3 + 1], b2 = xr[(j0 + r) * 3 + 2];
        Qs[r][32] = tf32r(a0 * cs); Qs[r][33] = tf32r(a1 * cs); Qs[r][34] = tf32r(a2 * cs);
        Qs[r][35] = tf32r(dcoef * (a0 * a0 + a1 * a1 + a2 * a2));
        Qs[r][36] = 1.0f; Qs[r][37] = 0.0f; Qs[r][38] = 0.0f; Qs[r][39] = 0.0f;
        Ks[r][32] = tf32r(b0 * cs); Ks[r][33] = tf32r(b1 * cs); Ks[r][34] = tf32r(b2 * cs);
        Ks[r][35] = 1.0f;
        Ks[r][36] = tf32r(dcoef * (b0 * b0 + b1 * b1 + b2 * b2));
        Ks[r][37] = 0.0f; Ks[r][38] = 0.0f; Ks[r][39] = 0.0f;
        mi[r] = mask[i0 + r];
        mj[r] = mask[j0 + r];
    }
    if (tid < NBINS) pwie[tid] = pw[tid * HH + h] * ie;
    __syncthreads();

    float d[2][2][4];
#pragma unroll
    for (int mt = 0; mt < 2; ++mt)
#pragma unroll
        for (int nt = 0; nt < 2; ++nt)
#pragma unroll
            for (int q = 0; q < 4; ++q) d[mt][nt][q] = 0.0f;

#pragma unroll
    for (int ks = 0; ks < 5; ++ks) {
        int kb = ks * 8;
        uint32_t a[2][4], b[2][2];
#pragma unroll
        for (int mt = 0; mt < 2; ++mt) {
            int r = warpM * 32 + mt * 16 + (lane >> 2);
            int c = kb + (lane & 3);
            a[mt][0] = __float_as_uint(Qs[r][c]);
            a[mt][1] = __float_as_uint(Qs[r + 8][c]);
            a[mt][2] = __float_as_uint(Qs[r][c + 4]);
            a[mt][3] = __float_as_uint(Qs[r + 8][c + 4]);
        }
#pragma unroll
        for (int nt = 0; nt < 2; ++nt) {
            int r = warpN * 16 + nt * 8 + (lane >> 2);
            int c = kb + (lane & 3);
            b[nt][0] = __float_as_uint(Ks[r][c]);
            b[nt][1] = __float_as_uint(Ks[r][c + 4]);
        }
#pragma unroll
        for (int mt = 0; mt < 2; ++mt)
#pragma unroll
            for (int nt = 0; nt < 2; ++nt) mma_tf32(d[mt][nt], a[mt], b[nt]);
    }

#pragma unroll
    for (int mt = 0; mt < 2; ++mt) {
#pragma unroll
        for (int nt = 0; nt < 2; ++nt) {
#pragma unroll
            for (int half = 0; half < 2; ++half) {
                int il = warpM * 32 + mt * 16 + (lane >> 2) + half * 8;
                int jl = warpN * 16 + nt * 8 + (lane & 3) * 2;
                int i = i0 + il, j = j0 + jl;
                int2 bn2 = *(const int2*)&bins[i * NN + j];
                float l0 = d[mt][nt][half * 2 + 0] + pwie[bn2.x];
                float l1 = d[mt][nt][half * 2 + 1] + pwie[bn2.y];
                float lk0 = (mi[il] * mj[jl] > 0.0f) ? l0 : -1e9f;
                float lk1 = (mi[il] * mj[jl + 1] > 0.0f) ? l1 : -1e9f;
                __half2 e2 = __floats2half2_rn(__expf(lk0), __expf(lk1));
                *(__half2*)&EK[(h * NN + i) * NN + j] = e2;
            }
        }
    }
}

// ---------------------------------------------------------------------------
__global__ void skprep_kernel(const float* __restrict__ mu, const float* __restrict__ nu,
                              const float* __restrict__ lup, const float* __restrict__ lvp) {
    int idx = blockIdx.x * 256 + threadIdx.x;
    if (idx >= HH * NN) return;
    g_buf[OFF_LOGMU + idx] = logf(fmaxf(mu[idx], 1e-8f));
    g_buf[OFF_LOGNU + idx] = logf(fmaxf(nu[idx], 1e-8f));
    g_buf[OFF_U + idx] = lup[idx];
    g_buf[OFF_V2 + idx] = lvp[idx];
    g_buf[OFF_EU + idx] = __expf(lup[idx]);
    g_buf[OFF_EV + idx] = __expf(lvp[idx]);
}

// log_u[h,i] = fi*(log_mu - log(sum_j E[h,i,j]*ev[h,j])); also eu = exp(log_u).
__global__ void __launch_bounds__(256) sk_u_kernel(const float* __restrict__ eps) {
    __shared__ float sv[NN];
    int h = blockIdx.y;
    for (int t = threadIdx.x; t < NN; t += 256) sv[t] = g_buf[OFF_EV + h * NN + t];
    __syncthreads();
    const __half* EK = (const __half*)(g_buf + OFF_EK);
    int w = threadIdx.x >> 5, lane = threadIdx.x & 31;
    int i = blockIdx.x * 16 + w * 2;
    const uint4* row0 = (const uint4*)(EK + (h * NN + i) * NN);
    const uint4* row1 = (const uint4*)(EK + (h * NN + i + 1) * NN);
    float s0 = 0.0f, s1 = 0.0f;
#pragma unroll
    for (int q = 0; q < 4; ++q) {
        uint4 pk0 = row0[q * 32 + lane];
        uint4 pk1 = row1[q * 32 + lane];
        int jb = (q * 32 + lane) * 8;
        float4 v0 = *(const float4*)&sv[jb];
        float4 v1 = *(const float4*)&sv[jb + 4];
        {
            float2 e0 = __half22float2(*(const __half2*)&pk0.x);
            float2 e1 = __half22float2(*(const __half2*)&pk0.y);
            float2 e2 = __half22float2(*(const __half2*)&pk0.z);
            float2 e3 = __half22float2(*(const __half2*)&pk0.w);
            s0 += e0.x * v0.x + e0.y * v0.y + e1.x * v0.z + e1.y * v0.w;
            s0 += e2.x * v1.x + e2.y * v1.y + e3.x * v1.z + e3.y * v1.w;
        }
        {
            float2 e0 = __half22float2(*(const __half2*)&pk1.x);
            float2 e1 = __half22float2(*(const __half2*)&pk1.y);
            float2 e2 = __half22float2(*(const __half2*)&pk1.z);
            float2 e3 = __half22float2(*(const __half2*)&pk1.w);
            s1 += e0.x * v0.x + e0.y * v0.y + e1.x * v0.z + e1.y * v0.w;
            s1 += e2.x * v1.x + e2.y * v1.y + e3.x * v1.z + e3.y * v1.w;
        }
    }
#pragma unroll
    for (int o = 16; o; o >>= 1) {
        s0 += __shfl_xor_sync(0xffffffffu, s0, o);
        s1 += __shfl_xor_sync(0xffffffffu, s1, o);
    }
    if (lane == 0) {
        float fi = 1.0f / (1.0f + eps[h]);
        float u0 = fi * (g_buf[OFF_LOGMU + h * NN + i] - logf(s0));
        float u1 = fi * (g_buf[OFF_LOGMU + h * NN + i + 1] - logf(s1));
        g_buf[OFF_U + h * NN + i] = u0;
        g_buf[OFF_U + h * NN + i + 1] = u1;
        g_buf[OFF_EU + h * NN + i] = __expf(u0);
        g_buf[OFF_EU + h * NN + i + 1] = __expf(u1);
    }
}

// log_v[h,j] = fi*(log_nu - log(sum_i E[h,i,j]*eu[h,i])); also ev = exp(log_v).
__global__ void __launch_bounds__(256) sk_v_kernel(const float* __restrict__ eps) {
    __shared__ float su[NN];
    __shared__ float rsum[8][66];
    int h = blockIdx.y;
    for (int t = threadIdx.x; t < NN; t += 256) su[t] = g_buf[OFF_EU + h * NN + t];
    __syncthreads();
    const __half* EK = (const __half*)(g_buf + OFF_EK);
    int lane = threadIdx.x & 31, w = threadIdx.x >> 5;
    int jb = blockIdx.x * 64;
    const __half2* col = (const __half2*)(EK + h * NN * NN + jb) + lane;
    float s0 = 0.0f, s1 = 0.0f;
    int i0 = w * 128;
#pragma unroll 4
    for (int t = 0; t < 128; ++t) {
        int i = i0 + t;
        float2 e = __half22float2(col[i * (NN / 2)]);
        float uu = su[i];
        s0 += e.x * uu;
        s1 += e.y * uu;
    }
    rsum[w][lane * 2] = s0;
    rsum[w][lane * 2 + 1] = s1;
    __syncthreads();
    if (threadIdx.x < 64) {
        int jx = threadIdx.x;
        float S = rsum[0][jx];
#pragma unroll
        for (int k = 1; k < 8; ++k) S += rsum[k][jx];
        float fi = 1.0f / (1.0f + eps[h]);
        float vv = fi * (g_buf[OFF_LOGNU + h * NN + jb + jx] - logf(S));
        g_buf[OFF_V2 + h * NN + jb + jx] = vv;
        g_buf[OFF_EV + h * NN + jb + jx] = __expf(vv);
    }
}

__global__ void copyuv_kernel(float* __restrict__ out) {
    int idx = blockIdx.x * 256 + threadIdx.x;
    if (idx >= HH * NN) return;
    out[OUT_U + idx] = g_buf[OFF_U + idx];
    out[OUT_V + idx] = g_buf[OFF_V2 + idx];
}

// ---------------------------------------------------------------------------
// Pack Vx[h][j][c]: c<32 -> V head slice, c=32..34 -> x_res
__global__ void pack_kernel(const float* __restrict__ xr) {
    int idx = blockIdx.x * 256 + threadIdx.x;
    if (idx >= HH * NN * 35) return;
    int c = idx % 35;
    int hj = idx / 35;
    int j = hj & (NN - 1);
    int h = hj >> 10;
    float v = (c < 32) ? g_buf[OFF_V + j * DD + h * DH + c] : xr[j * 3 + (c - 32)];
    g_buf[OFF_VXP + idx] = v;
}

// Fused: P = E*eu*ev, rowsum clip, attn = Pn@V * sigmoid(G), x_cent = Pn@x_res.
// 1024 blocks = 16 heads x 64 row-blocks of 16 rows. Warp handles 2 rows.
// E read as half2 (2 j per lane).
__global__ void __launch_bounds__(256, 2) attn_kernel() {
    __shared__ float sVx[256 * 36];
    __shared__ float sv[256];
    const __half* EK = (const __half*)(g_buf + OFF_EK);
    int h = blockIdx.x >> 6;
    int w = threadIdx.x >> 5, lane = threadIdx.x & 31;
    int i0 = (blockIdx.x & 63) * 16 + w * 2;
    float eu0 = g_buf[OFF_EU + h * NN + i0 + 0];
    float eu1 = g_buf[OFF_EU + h * NN + i0 + 1];
    const __half* lk0 = EK + (h * NN + i0) * NN;

    float acc[2][36];
#pragma unroll
    for (int r = 0; r < 2; ++r)
#pragma unroll
        for (int c = 0; c < 36; ++c) acc[r][c] = 0.0f;
    float rs0 = 0.f, rs1 = 0.f;

    for (int cb = 0; cb < 4; ++cb) {
        int jb = cb * 256;
        __syncthreads();
        const float* src = g_buf + OFF_VXP + (h * NN + jb) * 35;
        for (int t = threadIdx.x; t < 256 * 35; t += 256) {
            int jo = t / 35, c = t - jo * 35;
            sVx[jo * 36 + c] = src[t];
        }
        sv[threadIdx.x] = g_buf[OFF_EV + h * NN + jb + threadIdx.x];
        __syncthreads();
#pragma unroll 1
        for (int s = 0; s < 4; ++s) {
            int jl = s * 64 + lane * 2;
            int j = jb + jl;
            float2 e0 = __half22float2(*(const __half2*)&lk0[j]);
            float2 e1 = __half22float2(*(const __half2*)&lk0[NN + j]);
            float vj0 = sv[jl], vj1 = sv[jl + 1];
            float p00 = e0.x * vj0, p01 = e0.y * vj1;
            float p10 = e1.x * vj0, p11 = e1.y * vj1;
            rs0 += p00 + p01; rs1 += p10 + p11;
            const float4* vp0 = (const float4*)(sVx + jl * 36);
            const float4* vp1 = (const float4*)(sVx + (jl + 1) * 36);
#pragma unroll
            for (int c4 = 0; c4 < 9; ++c4) {
                float4 a0 = vp0[c4];
                float4 a1 = vp1[c4];
                acc[0][c4 * 4 + 0] += p00 * a0.x + p01 * a1.x;
                acc[0][c4 * 4 + 1] += p00 * a0.y + p01 * a1.y;
                acc[0][c4 * 4 + 2] += p00 * a0.z + p01 * a1.z;
                acc[0][c4 * 4 + 3] += p00 * a0.w + p01 * a1.w;
                acc[1][c4 * 4 + 0] += p10 * a0.x + p11 * a1.x;
                acc[1][c4 * 4 + 1] += p10 * a0.y + p11 * a1.y;
                acc[1][c4 * 4 + 2] += p10 * a0.z + p11 * a1.z;
                acc[1][c4 * 4 + 3] += p10 * a0.w + p11 * a1.w;
            }
        }
    }

    // Pn_ij = (E_ij*ev_j*eu_i) / max(eu_i*rs_i, 1e-8)
    float rsv[2] = {rs0, rs1};
    float euv[2] = {eu0, eu1};
#pragma unroll
    for (int r = 0; r < 2; ++r) {
        float t = rsv[r];
#pragma unroll
        for (int o = 16; o; o >>= 1) t += __shfl_xor_sync(0xffffffffu, t, o);
        rsv[r] = t;
    }
#pragma unroll
    for (int r = 0; r < 2; ++r) {
        int i = i0 + r;
        float inv = euv[r] / fmaxf(euv[r] * rsv[r], 1e-8f);
#pragma unroll
        for (int c = 0; c < 35; ++c) {
            float a = acc[r][c];
#pragma unroll
            for (int o = 16; o; o >>= 1) a += __shfl_xor_sync(0xffffffffu, a, o);
            if (c < 32) {
                if (lane == c) {
                    float g = g_buf[OFF_G + i * DD + h * DH + c];
                    float sg = 1.0f / (1.0f + __expf(-g));
                    g_buf[OFF_ATTN + i * DD + h * DH + c] = a * inv * sg;
                }
            } else {
                if (lane == c - 32) {
                    g_buf[OFF_XC + (h * NN + i) * 3 + (c - 32)] = a * inv;
                }
            }
        }
    }
}

// ---------------------------------------------------------------------------
__global__ void xupd_kernel(const float* __restrict__ xr, const float* __restrict__ mask,
                            const float* __restrict__ gamma, float* __restrict__ out) {
    int i = blockIdx.x * 256 + threadIdx.x;
    if (i >= NN) return;
    float x0 = xr[i * 3 + 0], x1 = xr[i * 3 + 1], x2 = xr[i * 3 + 2];
    float a0 = 0.f, a1 = 0.f, a2 = 0.f;
#pragma unroll
    for (int h = 0; h < HH; ++h) {
        float th = tanhf(gamma[h]) * (1.0f / HH);
        const float* xc = g_buf + OFF_XC + (h * NN + i) * 3;
        a0 += th * (x0 - xc[0]);
        a1 += th * (x1 - xc[1]);
        a2 += th * (x2 - xc[2]);
    }
    float mk = mask[i];
    out[i * 3 + 0] = x0 + a0 * mk;
    out[i * 3 + 1] = x1 + a1 * mk;
    out[i * 3 + 2] = x2 + a2 * mk;
}

__global__ void silu_kernel() {
    int idx = blockIdx.x * 256 + threadIdx.x;
    if (idx >= NN * 4 * DD) return;
    float a = g_buf[OFF_FFA + idx];
    float b = g_buf[OFF_FFB + idx];
    g_buf[OFF_FFG + idx] = a * b / (1.0f + __expf(-a));
}

// ---------------------------------------------------------------------------
extern "C" void kernel_launch(void* const* d_in, const int* in_sizes, int n_in,
                              void* d_out, int out_size) {
    const float* h    = (const float*)d_in[0];
    const float* xres = (const float*)d_in[1];
    const float* mu   = (const float*)d_in[2];
    const float* nu   = (const float*)d_in[3];
    const float* lup  = (const float*)d_in[4];
    const float* lvp  = (const float*)d_in[5];
    const float* mask = (const float*)d_in[6];
    const float* lnw  = (const float*)d_in[7];
    const float* lnb  = (const float*)d_in[8];
    const float* wq   = (const float*)d_in[9];
    const float* wk   = (const float*)d_in[10];
    const float* wv   = (const float*)d_in[11];
    const float* wg   = (const float*)d_in[12];
    const float* wo   = (const float*)d_in[13];
    const float* gamma= (const float*)d_in[14];
    const float* pw   = (const float*)d_in[15];
    const float* wdl  = (const float*)d_in[16];
    const float* lnfw = (const float*)d_in[17];
    const float* lnfb = (const float*)d_in[18];
    const float* w1   = (const float*)d_in[19];
    const float* w3   = (const float*)d_in[20];
    const float* w2   = (const float*)d_in[21];
    const int*   bins = (const int*)d_in[22];
    const float* eps  = (const float*)d_in[23];
    float* out = (float*)d_out;

    // 1. pre-LN
    ln_kernel<<<NN, 256>>>(h, 0, lnw, lnb, OFF_HN);

    // 2. fused Q|K|V|G projection: N=2048, segments land at OFF_Q..OFF_G
    tgemm_kernel<128, 128><<<dim3(16, 8), 256>>>(OFF_HN, wq, wk, wv, wg, DD,
                                                 OFF_Q, 0, 0, -1, 0, NN, DD);

    // 3. per-head plain LN on Q and K (one launch)
    headln_kernel<<<dim3(2048, 2), 256>>>(OFF_Q);

    // 4. E = exp(logK)  [fp16], full logit on tensor cores (K=40 augmented)
    logk_kernel<<<dim3(16, 16, 16), 256>>>(bins, pw, wdl, eps, mask, xres);

    // 5. Sinkhorn (pre-exp'd u/v vectors; single-wave u pass)
    skprep_kernel<<<64, 256>>>(mu, nu, lup, lvp);
    for (int it = 0; it < 20; ++it) {
        sk_u_kernel<<<dim3(64, 16), 256>>>(eps);
        sk_v_kernel<<<dim3(16, 16), 256>>>(eps);
    }
    copyuv_kernel<<<64, 256>>>(out);

    // 6. fused transport-plan attention + centroids
    pack_kernel<<<(HH * NN * 35 + 255) / 256, 256>>>(xres);
    attn_kernel<<<1024, 256>>>();
    xupd_kernel<<<4, 256>>>(xres, mask, gamma, out + OUT_X);

    // 7. output projection + residual
    tgemm_kernel<64, 64><<<dim3(8, 16), 256>>>(OFF_ATTN, wo, wo, wo, wo, DD,
                                               OFF_HMID, 0, h, -1, mask, NN, DD);

    // 8. FFN
    ln_kernel<<<NN, 256>>>(0, OFF_HMID, lnfw, lnfb, OFF_H2);
    tgemm_kernel<128, 128><<<dim3(32, 8), 256>>>(OFF_H2, w1, w3, w1, w1, 4 * DD,
                                                 OFF_FFA, 0, 0, -1, 0, NN, DD);
    silu_kernel<<<(NN * 4 * DD + 255) / 256, 256>>>();
    tgemm_kernel<64, 64><<<dim3(8, 16), 256>>>(OFF_FFG, w2, w2, w2, w2, DD,
                                               0, out + OUT_H, 0, OFF_HMID, mask, NN, 4 * DD);
}

// round 16
// speedup vs baseline: 1.0200x; 1.0200x over previous
#include <cuda_runtime.h>
#include <cuda_fp16.h>
#include <math.h>
#include <stdint.h>

#define NN 1024
#define DD 512
#define HH 16
#define DH 32
#define NBINS 68

// ---- scratch layout (float offsets into one big __device__ buffer) ----
#define OFF_HN     0
#define OFF_Q      524288
#define OFF_K      1048576
#define OFF_V      1572864
#define OFF_G      2097152
#define OFF_EK     2621440          /* E = exp(logK) fp16: 16M halves = 8M floats */
#define OFF_EU     11010048         /* exp(log_u), 16*1024 */
#define OFF_EV     11026432         /* exp(log_v), 16*1024 */
#define OFF_LOGMU  19398656
#define OFF_LOGNU  19415040
#define OFF_U      19431424
#define OFF_V2     19447808
#define OFF_VXP    19464192
#define OFF_ATTN   20037632
#define OFF_XC     20561920
#define OFF_HMID   20611072
#define OFF_H2     21135360
#define OFF_FFA    21659648
#define OFF_FFB    23756800
#define OFF_FFG    25853952
#define BUF_TOTAL  27951104

__device__ float g_buf[BUF_TOTAL];

// Output layout: [h | x_res | log_u | log_v]
#define OUT_H 0
#define OUT_X 524288
#define OUT_U 527360
#define OUT_V 543744

// ---------------------------------------------------------------------------
__device__ __forceinline__ float tf32r(float x) {
    uint32_t u;
    asm("cvt.rna.tf32.f32 %0, %1;" : "=r"(u) : "f"(x));
    return __uint_as_float(u);
}

__device__ __forceinline__ uint32_t tf32u(float x) {
    uint32_t u;
    asm("cvt.rna.tf32.f32 %0, %1;" : "=r"(u) : "f"(x));
    return u;
}

__device__ __forceinline__ void mma_tf32(float* d, const uint32_t* a, const uint32_t* b) {
    asm volatile(
        "mma.sync.aligned.m16n8k8.row.col.f32.tf32.tf32.f32 "
        "{%0,%1,%2,%3}, {%4,%5,%6,%7}, {%8,%9}, {%0,%1,%2,%3};"
        : "+f"(d[0]), "+f"(d[1]), "+f"(d[2]), "+f"(d[3])
        : "r"(a[0]), "r"(a[1]), "r"(a[2]), "r"(a[3]), "r"(b[0]), "r"(b[1]));
}

#define CP_ASYNC16(smem_u32, gptr) \
    asm volatile("cp.async.cg.shared.global [%0], [%1], 16;" :: "r"(smem_u32), "l"(gptr))
#define CP_COMMIT() asm volatile("cp.async.commit_group;")
#define CP_WAIT(n)  asm volatile("cp.async.wait_group %0;" :: "n"(n))

// ---------------------------------------------------------------------------
// LayerNorm over last dim D=512. One block per row, 256 threads.
__global__ void ln_kernel(const float* __restrict__ inExt, int inOff,
                          const float* __restrict__ w, const float* __restrict__ b,
                          int outOff) {
    const float* in = inExt ? inExt : (g_buf + inOff);
    int row = blockIdx.x, tid = threadIdx.x;
    __shared__ float red[256];
    float x0 = in[row * DD + tid];
    float x1 = in[row * DD + 256 + tid];
    red[tid] = x0 + x1;
    __syncthreads();
    for (int o = 128; o; o >>= 1) { if (tid < o) red[tid] += red[tid + o]; __syncthreads(); }
    float m = red[0] * (1.0f / DD);
    __syncthreads();
    float d0 = x0 - m, d1 = x1 - m;
    red[tid] = d0 * d0 + d1 * d1;
    __syncthreads();
    for (int o = 128; o; o >>= 1) { if (tid < o) red[tid] += red[tid + o]; __syncthreads(); }
    float var = red[0] * (1.0f / DD);
    float rs = rsqrtf(var + 1e-5f);
    float* out = g_buf + outOff;
    out[row * DD + tid]       = d0 * rs * w[tid]       + b[tid];
    out[row * DD + 256 + tid] = d1 * rs * w[tid + 256] + b[tid + 256];
}

// ---------------------------------------------------------------------------
// TF32 tensor-core GEMM, double-buffered cp.async pipeline.
template<int BM, int BN>
__global__ void __launch_bounds__(256) tgemm_kernel(
    int aOff, const float* __restrict__ B0, const float* __restrict__ B1,
    const float* __restrict__ B2, const float* __restrict__ B3,
    int nPerW, int cOff, float* __restrict__ outExt,
    const float* __restrict__ resExt, int resOff,
    const float* __restrict__ mask, int M, int K) {
    constexpr int BK = 16;
    constexpr int WM = BM / 2, WN = BN / 4;
    constexpr int MT = WM / 16, NT = WN / 8;
    __shared__ float As[2][BM][BK + 4];
    __shared__ float Bs[2][BN][BK + 4];
    const float* A = g_buf + aOff;
    int m0 = blockIdx.y * BM, n0 = blockIdx.x * BN;
    int widx = n0 / nPerW;
    const float* Bw = (widx == 0) ? B0 : (widx == 1) ? B1 : (widx == 2) ? B2 : B3;
    int nloc0 = n0 - widx * nPerW;

    int tid = threadIdx.x, lane = tid & 31, wid = tid >> 5;
    int warpM = wid >> 2, warpN = wid & 3;

    int rA = tid >> 2, kqA = (tid & 3) << 2;

    float d[MT][NT][4];
#pragma unroll
    for (int mt = 0; mt < MT; ++mt)
#pragma unroll
        for (int nt = 0; nt < NT; ++nt)
#pragma unroll
            for (int q = 0; q < 4; ++q) d[mt][nt][q] = 0.0f;

    const int KT = K / BK;

    {
#pragma unroll
        for (int t0 = 0; t0 < BM * 4; t0 += 256) {
            int r = rA + (t0 >> 2);
            uint32_t sa = (uint32_t)__cvta_generic_to_shared(&As[0][r][kqA]);
            CP_ASYNC16(sa, &A[(m0 + r) * K + kqA]);
        }
#pragma unroll
        for (int t0 = 0; t0 < BN * 4; t0 += 256) {
            int r = rA + (t0 >> 2);
            uint32_t sa = (uint32_t)__cvta_generic_to_shared(&Bs[0][r][kqA]);
            CP_ASYNC16(sa, &Bw[(nloc0 + r) * K + kqA]);
        }
        CP_COMMIT();
    }

    for (int kt = 0; kt < KT; ++kt) {
        int st = kt & 1;
        if (kt + 1 < KT) {
            int k0n = (kt + 1) * BK;
            int sn = st ^ 1;
#pragma unroll
            for (int t0 = 0; t0 < BM * 4; t0 += 256) {
                int r = rA + (t0 >> 2);
                uint32_t sa = (uint32_t)__cvta_generic_to_shared(&As[sn][r][kqA]);
                CP_ASYNC16(sa, &A[(m0 + r) * K + k0n + kqA]);
            }
#pragma unroll
            for (int t0 = 0; t0 < BN * 4; t0 += 256) {
                int r = rA + (t0 >> 2);
                uint32_t sa = (uint32_t)__cvta_generic_to_shared(&Bs[sn][r][kqA]);
                CP_ASYNC16(sa, &Bw[(nloc0 + r) * K + k0n + kqA]);
            }
            CP_COMMIT();
            CP_WAIT(1);
        } else {
            CP_WAIT(0);
        }
        __syncthreads();
#pragma unroll
        for (int ks = 0; ks < 2; ++ks) {
            int kb = ks * 8;
            uint32_t a[MT][4], b[NT][2];
#pragma unroll
            for (int mt = 0; mt < MT; ++mt) {
                int r = warpM * WM + mt * 16 + (lane >> 2);
                int c = kb + (lane & 3);
                a[mt][0] = tf32u(As[st][r][c]);
                a[mt][1] = tf32u(As[st][r + 8][c]);
                a[mt][2] = tf32u(As[st][r][c + 4]);
                a[mt][3] = tf32u(As[st][r + 8][c + 4]);
            }
#pragma unroll
            for (int nt = 0; nt < NT; ++nt) {
                int r = warpN * WN + nt * 8 + (lane >> 2);
                int c = kb + (lane & 3);
                b[nt][0] = tf32u(Bs[st][r][c]);
                b[nt][1] = tf32u(Bs[st][r][c + 4]);
            }
#pragma unroll
            for (int mt = 0; mt < MT; ++mt)
#pragma unroll
                for (int nt = 0; nt < NT; ++nt) mma_tf32(d[mt][nt], a[mt], b[nt]);
        }
        __syncthreads();
    }

    float* outp = (outExt ? outExt : (g_buf + cOff)) + (long)widx * M * nPerW;
    const float* resp = resExt ? resExt : (resOff >= 0 ? (g_buf + resOff) : (const float*)0);
#pragma unroll
    for (int mt = 0; mt < MT; ++mt) {
        int row0 = m0 + warpM * WM + mt * 16 + (lane >> 2);
#pragma unroll
        for (int nt = 0; nt < NT; ++nt) {
            int col = nloc0 + warpN * WN + nt * 8 + (lane & 3) * 2;
#pragma unroll
            for (int half = 0; half < 2; ++half) {
                int row = row0 + half * 8;
                float2 v = make_float2(d[mt][nt][half * 2], d[mt][nt][half * 2 + 1]);
                if (resp) {
                    float mk = mask ? mask[row] : 1.0f;
                    float2 r2 = *(const float2*)&resp[row * nPerW + col];
                    v.x = r2.x + v.x * mk;
                    v.y = r2.y + v.y * mk;
                }
                *(float2*)&outp[row * nPerW + col] = v;
            }
        }
    }
}

// ---------------------------------------------------------------------------
// Per-head plain LN over DH=32; grid (2048, 2): y=0 -> Q, y=1 -> K.
__global__ void headln_kernel(int off0) {
    int off = off0 + (int)blockIdx.y * (NN * DD);
    int gid = blockIdx.x * 8 + (threadIdx.x >> 5);
    int lane = threadIdx.x & 31;
    int i = gid >> 4, h = gid & 15;
    float* p = g_buf + off + i * DD + h * DH + lane;
    float x = *p;
    float s = x;
#pragma unroll
    for (int o = 16; o; o >>= 1) s += __shfl_xor_sync(0xffffffffu, s, o);
    float m = s * (1.0f / DH);
    float d = x - m;
    float v = d * d;
#pragma unroll
    for (int o = 16; o; o >>= 1) v += __shfl_xor_sync(0xffffffffu, v, o);
    float var = v * (1.0f / DH);
    *p = d * rsqrtf(var + 1e-5f);
}

// ---------------------------------------------------------------------------
// E[h,i,j] = exp(pair_mask ? (QK/sqrt32 + bias - wd*d2/100)/eps : -1e9) [fp16]
// Full logit (minus bias) computed on tensor cores via augmented K=40.
__global__ void __launch_bounds__(256) logk_kernel(
    const int* __restrict__ bins, const float* __restrict__ pw,
    const float* __restrict__ wdl, const float* __restrict__ eps,
    const float* __restrict__ mask, const float* __restrict__ xr) {
    __shared__ float Qs[64][44], Ks[64][44];
    __shared__ float mi[64], mj[64], pwie[NBINS];
    __half* EK = (__half*)(g_buf + OFF_EK);
    int h = blockIdx.z, i0 = blockIdx.y * 64, j0 = blockIdx.x * 64;
    int tid = threadIdx.x, lane = tid & 31, wid = tid >> 5;
    int warpM = wid >> 2, warpN = wid & 3;

    float wd = 1.0f / (1.0f + expf(-wdl[h]));
    float ie = 1.0f / eps[h];
    const float s32 = 0.17677669529663687f;  // 1/sqrt(32)
    float qscale = s32 * ie;
    float cs = sqrtf(0.02f * wd * ie);
    float dcoef = -0.01f * wd * ie;

    for (int t = tid; t < 512; t += 256) {
        int r = t >> 3, kq = (t & 7) << 2;
        float4 q4 = *(const float4*)&g_buf[OFF_Q + (i0 + r) * DD + h * DH + kq];
        float4 k4 = *(const float4*)&g_buf[OFF_K + (j0 + r) * DD + h * DH + kq];
        Qs[r][kq + 0] = tf32r(q4.x * qscale); Qs[r][kq + 1] = tf32r(q4.y * qscale);
        Qs[r][kq + 2] = tf32r(q4.z * qscale); Qs[r][kq + 3] = tf32r(q4.w * qscale);
        Ks[r][kq + 0] = tf32r(k4.x); Ks[r][kq + 1] = tf32r(k4.y);
        Ks[r][kq + 2] = tf32r(k4.z); Ks[r][kq + 3] = tf32r(k4.w);
    }
    if (tid < 64) {
        int r = tid;
        float a0 = xr[(i0 + r) * 3 + 0], a1 = xr[(i0 + r) * 3 + 1], a2 = xr[(i0 + r) * 3 + 2];
        float b0 = xr[(j0 + r) * 3 + 0], b1 = xr[(j0 + r) * 3 + 1], b2 = xr[(j0 + r) * 3 + 2];
        Qs[r][32] = tf32r(a0 * cs); Qs[r][33] = tf32r(a1 * cs); Qs[r][34] = tf32r(a2 * cs);
        Qs[r][35] = tf32r(dcoef * (a0 * a0 + a1 * a1 + a2 * a2));
        Qs[r][36] = 1.0f; Qs[r][37] = 0.0f; Qs[r][38] = 0.0f; Qs[r][39] = 0.0f;
        Ks[r][32] = tf32r(b0 * cs); Ks[r][33] = tf32r(b1 * cs); Ks[r][34] = tf32r(b2 * cs);
        Ks[r][35] = 1.0f;
        Ks[r][36] = tf32r(dcoef * (b0 * b0 + b1 * b1 + b2 * b2));
        Ks[r][37] = 0.0f; Ks[r][38] = 0.0f; Ks[r][39] = 0.0f;
        mi[r] = mask[i0 + r];
        mj[r] = mask[j0 + r];
    }
    if (tid < NBINS) pwie[tid] = pw[tid * HH + h] * ie;
    __syncthreads();

    float d[2][2][4];
#pragma unroll
    for (int mt = 0; mt < 2; ++mt)
#pragma unroll
        for (int nt = 0; nt < 2; ++nt)
#pragma unroll
            for (int q = 0; q < 4; ++q) d[mt][nt][q] = 0.0f;

#pragma unroll
    for (int ks = 0; ks < 5; ++ks) {
        int kb = ks * 8;
        uint32_t a[2][4], b[2][2];
#pragma unroll
        for (int mt = 0; mt < 2; ++mt) {
            int r = warpM * 32 + mt * 16 + (lane >> 2);
            int c = kb + (lane & 3);
            a[mt][0] = __float_as_uint(Qs[r][c]);
            a[mt][1] = __float_as_uint(Qs[r + 8][c]);
            a[mt][2] = __float_as_uint(Qs[r][c + 4]);
            a[mt][3] = __float_as_uint(Qs[r + 8][c + 4]);
        }
#pragma unroll
        for (int nt = 0; nt < 2; ++nt) {
            int r = warpN * 16 + nt * 8 + (lane >> 2);
            int c = kb + (lane & 3);
            b[nt][0] = __float_as_uint(Ks[r][c]);
            b[nt][1] = __float_as_uint(Ks[r][c + 4]);
        }
#pragma unroll
        for (int mt = 0; mt < 2; ++mt)
#pragma unroll
            for (int nt = 0; nt < 2; ++nt) mma_tf32(d[mt][nt], a[mt], b[nt]);
    }

#pragma unroll
    for (int mt = 0; mt < 2; ++mt) {
#pragma unroll
        for (int nt = 0; nt < 2; ++nt) {
#pragma unroll
            for (int half = 0; half < 2; ++half) {
                int il = warpM * 32 + mt * 16 + (lane >> 2) + half * 8;
                int jl = warpN * 16 + nt * 8 + (lane & 3) * 2;
                int i = i0 + il, j = j0 + jl;
                int2 bn2 = *(const int2*)&bins[i * NN + j];
                float l0 = d[mt][nt][half * 2 + 0] + pwie[bn2.x];
                float l1 = d[mt][nt][half * 2 + 1] + pwie[bn2.y];
                float lk0 = (mi[il] * mj[jl] > 0.0f) ? l0 : -1e9f;
                float lk1 = (mi[il] * mj[jl + 1] > 0.0f) ? l1 : -1e9f;
                __half2 e2 = __floats2half2_rn(__expf(lk0), __expf(lk1));
                *(__half2*)&EK[(h * NN + i) * NN + j] = e2;
            }
        }
    }
}

// ---------------------------------------------------------------------------
__global__ void skprep_kernel(const float* __restrict__ mu, const float* __restrict__ nu,
                              const float* __restrict__ lup, const float* __restrict__ lvp) {
    int idx = blockIdx.x * 256 + threadIdx.x;
    if (idx >= HH * NN) return;
    g_buf[OFF_LOGMU + idx] = logf(fmaxf(mu[idx], 1e-8f));
    g_buf[OFF_LOGNU + idx] = logf(fmaxf(nu[idx], 1e-8f));
    g_buf[OFF_U + idx] = lup[idx];
    g_buf[OFF_V2 + idx] = lvp[idx];
    g_buf[OFF_EU + idx] = __expf(lup[idx]);
    g_buf[OFF_EV + idx] = __expf(lvp[idx]);
}

// log_u[h,i] = fi*(log_mu - log(sum_j E[h,i,j]*ev[h,j])); also eu = exp(log_u).
__global__ void __launch_bounds__(256) sk_u_kernel(const float* __restrict__ eps) {
    __shared__ float sv[NN];
    int h = blockIdx.y;
    for (int t = threadIdx.x; t < NN; t += 256) sv[t] = g_buf[OFF_EV + h * NN + t];
    __syncthreads();
    const __half* EK = (const __half*)(g_buf + OFF_EK);
    int w = threadIdx.x >> 5, lane = threadIdx.x & 31;
    int i = blockIdx.x * 16 + w * 2;
    const uint4* row0 = (const uint4*)(EK + (h * NN + i) * NN);
    const uint4* row1 = (const uint4*)(EK + (h * NN + i + 1) * NN);
    float s0 = 0.0f, s1 = 0.0f;
#pragma unroll
    for (int q = 0; q < 4; ++q) {
        uint4 pk0 = row0[q * 32 + lane];
        uint4 pk1 = row1[q * 32 + lane];
        int jb = (q * 32 + lane) * 8;
        float4 v0 = *(const float4*)&sv[jb];
        float4 v1 = *(const float4*)&sv[jb + 4];
        {
            float2 e0 = __half22float2(*(const __half2*)&pk0.x);
            float2 e1 = __half22float2(*(const __half2*)&pk0.y);
            float2 e2 = __half22float2(*(const __half2*)&pk0.z);
            float2 e3 = __half22float2(*(const __half2*)&pk0.w);
            s0 += e0.x * v0.x + e0.y * v0.y + e1.x * v0.z + e1.y * v0.w;
            s0 += e2.x * v1.x + e2.y * v1.y + e3.x * v1.z + e3.y * v1.w;
        }
        {
            float2 e0 = __half22float2(*(const __half2*)&pk1.x);
            float2 e1 = __half22float2(*(const __half2*)&pk1.y);
            float2 e2 = __half22float2(*(const __half2*)&pk1.z);
            float2 e3 = __half22float2(*(const __half2*)&pk1.w);
            s1 += e0.x * v0.x + e0.y * v0.y + e1.x * v0.z + e1.y * v0.w;
            s1 += e2.x * v1.x + e2.y * v1.y + e3.x * v1.z + e3.y * v1.w;
        }
    }
#pragma unroll
    for (int o = 16; o; o >>= 1) {
        s0 += __shfl_xor_sync(0xffffffffu, s0, o);
        s1 += __shfl_xor_sync(0xffffffffu, s1, o);
    }
    if (lane == 0) {
        float fi = 1.0f / (1.0f + eps[h]);
        float u0 = fi * (g_buf[OFF_LOGMU + h * NN + i] - logf(s0));
        float u1 = fi * (g_buf[OFF_LOGMU + h * NN + i + 1] - logf(s1));
        g_buf[OFF_U + h * NN + i] = u0;
        g_buf[OFF_U + h * NN + i + 1] = u1;
        g_buf[OFF_EU + h * NN + i] = __expf(u0);
        g_buf[OFF_EU + h * NN + i + 1] = __expf(u1);
    }
}

// log_v[h,j] = fi*(log_nu - log(sum_i E[h,i,j]*eu[h,i])); also ev = exp(log_v).
__global__ void __launch_bounds__(256) sk_v_kernel(const float* __restrict__ eps) {
    __shared__ float su[NN];
    __shared__ float rsum[8][66];
    int h = blockIdx.y;
    for (int t = threadIdx.x; t < NN; t += 256) su[t] = g_buf[OFF_EU + h * NN + t];
    __syncthreads();
    const __half* EK = (const __half*)(g_buf + OFF_EK);
    int lane = threadIdx.x & 31, w = threadIdx.x >> 5;
    int jb = blockIdx.x * 64;
    const __half2* col = (const __half2*)(EK + h * NN * NN + jb) + lane;
    float s0 = 0.0f, s1 = 0.0f;
    int i0 = w * 128;
#pragma unroll 4
    for (int t = 0; t < 128; ++t) {
        int i = i0 + t;
        float2 e = __half22float2(col[i * (NN / 2)]);
        float uu = su[i];
        s0 += e.x * uu;
        s1 += e.y * uu;
    }
    rsum[w][lane * 2] = s0;
    rsum[w][lane * 2 + 1] = s1;
    __syncthreads();
    if (threadIdx.x < 64) {
        int jx = threadIdx.x;
        float S = rsum[0][jx];
#pragma unroll
        for (int k = 1; k < 8; ++k) S += rsum[k][jx];
        float fi = 1.0f / (1.0f + eps[h]);
        float vv = fi * (g_buf[OFF_LOGNU + h * NN + jb + jx] - logf(S));
        g_buf[OFF_V2 + h * NN + jb + jx] = vv;
        g_buf[OFF_EV + h * NN + jb + jx] = __expf(vv);
    }
}

__global__ void copyuv_kernel(float* __restrict__ out) {
    int idx = blockIdx.x * 256 + threadIdx.x;
    if (idx >= HH * NN) return;
    out[OUT_U + idx] = g_buf[OFF_U + idx];
    out[OUT_V + idx] = g_buf[OFF_V2 + idx];
}

// ---------------------------------------------------------------------------
// Pack Vx[h][j][c]: c<32 -> V head slice, c=32..34 -> x_res
__global__ void pack_kernel(const float* __restrict__ xr) {
    int idx = blockIdx.x * 256 + threadIdx.x;
    if (idx >= HH * NN * 35) return;
    int c = idx % 35;
    int hj = idx / 35;
    int j = hj & (NN - 1);
    int h = hj >> 10;
    float v = (c < 32) ? g_buf[OFF_V + j * DD + h * DH + c] : xr[j * 3 + (c - 32)];
    g_buf[OFF_VXP + idx] = v;
}

// Fused: P = E*eu*ev, rowsum clip, attn = Pn@V * sigmoid(G), x_cent = Pn@x_res.
// 1024 blocks = 16 heads x 64 row-blocks of 16 rows. Warp handles 2 rows.
__global__ void __launch_bounds__(256, 2) attn_kernel() {
    __shared__ float sVx[256 * 36];
    __shared__ float sv[256];
    const __half* EK = (const __half*)(g_buf + OFF_EK);
    int h = blockIdx.x >> 6;
    int w = threadIdx.x >> 5, lane = threadIdx.x & 31;
    int i0 = (blockIdx.x & 63) * 16 + w * 2;
    float eu0 = g_buf[OFF_EU + h * NN + i0 + 0];
    float eu1 = g_buf[OFF_EU + h * NN + i0 + 1];
    const __half* lk0 = EK + (h * NN + i0) * NN;

    float acc[2][36];
#pragma unroll
    for (int r = 0; r < 2; ++r)
#pragma unroll
        for (int c = 0; c < 36; ++c) acc[r][c] = 0.0f;
    float rs0 = 0.f, rs1 = 0.f;

    for (int cb = 0; cb < 4; ++cb) {
        int jb = cb * 256;
        __syncthreads();
        const float* src = g_buf + OFF_VXP + (h * NN + jb) * 35;
        for (int t = threadIdx.x; t < 256 * 35; t += 256) {
            int jo = t / 35, c = t - jo * 35;
            sVx[jo * 36 + c] = src[t];
        }
        sv[threadIdx.x] = g_buf[OFF_EV + h * NN + jb + threadIdx.x];
        __syncthreads();
#pragma unroll 1
        for (int s = 0; s < 8; ++s) {
            int jl = s * 32 + lane;
            int j = jb + jl;
            float vj = sv[jl];
            float p0 = __half2float(lk0[j]) * vj;
            float p1 = __half2float(lk0[NN + j]) * vj;
            rs0 += p0; rs1 += p1;
            const float4* vp = (const float4*)(sVx + jl * 36);
#pragma unroll
            for (int c4 = 0; c4 < 9; ++c4) {
                float4 vv = vp[c4];
                acc[0][c4 * 4 + 0] += p0 * vv.x; acc[0][c4 * 4 + 1] += p0 * vv.y;
                acc[0][c4 * 4 + 2] += p0 * vv.z; acc[0][c4 * 4 + 3] += p0 * vv.w;
                acc[1][c4 * 4 + 0] += p1 * vv.x; acc[1][c4 * 4 + 1] += p1 * vv.y;
                acc[1][c4 * 4 + 2] += p1 * vv.z; acc[1][c4 * 4 + 3] += p1 * vv.w;
            }
        }
    }

    // Pn_ij = (E_ij*ev_j*eu_i) / max(eu_i*rs_i, 1e-8)
    float rsv[2] = {rs0, rs1};
    float euv[2] = {eu0, eu1};
#pragma unroll
    for (int r = 0; r < 2; ++r) {
        float t = rsv[r];
#pragma unroll
        for (int o = 16; o; o >>= 1) t += __shfl_xor_sync(0xffffffffu, t, o);
        rsv[r] = t;
    }
#pragma unroll
    for (int r = 0; r < 2; ++r) {
        int i = i0 + r;
        float inv = euv[r] / fmaxf(euv[r] * rsv[r], 1e-8f);
#pragma unroll
        for (int c = 0; c < 35; ++c) {
            float a = acc[r][c];
#pragma unroll
            for (int o = 16; o; o >>= 1) a += __shfl_xor_sync(0xffffffffu, a, o);
            if (c < 32) {
                if (lane == c) {
                    float g = g_buf[OFF_G + i * DD + h * DH + c];
                    float sg = 1.0f / (1.0f + __expf(-g));
                    g_buf[OFF_ATTN + i * DD + h * DH + c] = a * inv * sg;
                }
            } else {
                if (lane == c - 32) {
                    g_buf[OFF_XC + (h * NN + i) * 3 + (c - 32)] = a * inv;
                }
            }
        }
    }
}

// ---------------------------------------------------------------------------
__global__ void xupd_kernel(const float* __restrict__ xr, const float* __restrict__ mask,
                            const float* __restrict__ gamma, float* __restrict__ out) {
    int i = blockIdx.x * 256 + threadIdx.x;
    if (i >= NN) return;
    float x0 = xr[i * 3 + 0], x1 = xr[i * 3 + 1], x2 = xr[i * 3 + 2];
    float a0 = 0.f, a1 = 0.f, a2 = 0.f;
#pragma unroll
    for (int h = 0; h < HH; ++h) {
        float th = tanhf(gamma[h]) * (1.0f / HH);
        const float* xc = g_buf + OFF_XC + (h * NN + i) * 3;
        a0 += th * (x0 - xc[0]);
        a1 += th * (x1 - xc[1]);
        a2 += th * (x2 - xc[2]);
    }
    float mk = mask[i];
    out[i * 3 + 0] = x0 + a0 * mk;
    out[i * 3 + 1] = x1 + a1 * mk;
    out[i * 3 + 2] = x2 + a2 * mk;
}

__global__ void silu_kernel() {
    int idx = blockIdx.x * 256 + threadIdx.x;
    if (idx >= NN * 4 * DD) return;
    float a = g_buf[OFF_FFA + idx];
    float b = g_buf[OFF_FFB + idx];
    g_buf[OFF_FFG + idx] = a * b / (1.0f + __expf(-a));
}

// ---------------------------------------------------------------------------
extern "C" void kernel_launch(void* const* d_in, const int* in_sizes, int n_in,
                              void* d_out, int out_size) {
    const float* h    = (const float*)d_in[0];
    const float* xres = (const float*)d_in[1];
    const float* mu   = (const float*)d_in[2];
    const float* nu   = (const float*)d_in[3];
    const float* lup  = (const float*)d_in[4];
    const float* lvp  = (const float*)d_in[5];
    const float* mask = (const float*)d_in[6];
    const float* lnw  = (const float*)d_in[7];
    const float* lnb  = (const float*)d_in[8];
    const float* wq   = (const float*)d_in[9];
    const float* wk   = (const float*)d_in[10];
    const float* wv   = (const float*)d_in[11];
    const float* wg   = (const float*)d_in[12];
    const float* wo   = (const float*)d_in[13];
    const float* gamma= (const float*)d_in[14];
    const float* pw   = (const float*)d_in[15];
    const float* wdl  = (const float*)d_in[16];
    const float* lnfw = (const float*)d_in[17];
    const float* lnfb = (const float*)d_in[18];
    const float* w1   = (const float*)d_in[19];
    const float* w3   = (const float*)d_in[20];
    const float* w2   = (const float*)d_in[21];
    const int*   bins = (const int*)d_in[22];
    const float* eps  = (const float*)d_in[23];
    float* out = (float*)d_out;

    // 1. pre-LN
    ln_kernel<<<NN, 256>>>(h, 0, lnw, lnb, OFF_HN);

    // 2. fused Q|K|V|G projection: N=2048, segments land at OFF_Q..OFF_G
    tgemm_kernel<128, 128><<<dim3(16, 8), 256>>>(OFF_HN, wq, wk, wv, wg, DD,
                                                 OFF_Q, 0, 0, -1, 0, NN, DD);

    // 3. per-head plain LN on Q and K (one launch)
    headln_kernel<<<dim3(2048, 2), 256>>>(OFF_Q);

    // 4. E = exp(logK)  [fp16], full logit on tensor cores (K=40 augmented)
    logk_kernel<<<dim3(16, 16, 16), 256>>>(bins, pw, wdl, eps, mask, xres);

    // 5. Sinkhorn (pre-exp'd u/v vectors; single-wave u pass)
    skprep_kernel<<<64, 256>>>(mu, nu, lup, lvp);
    for (int it = 0; it < 20; ++it) {
        sk_u_kernel<<<dim3(64, 16), 256>>>(eps);
        sk_v_kernel<<<dim3(16, 16), 256>>>(eps);
    }
    copyuv_kernel<<<64, 256>>>(out);

    // 6. fused transport-plan attention + centroids
    pack_kernel<<<(HH * NN * 35 + 255) / 256, 256>>>(xres);
    attn_kernel<<<1024, 256>>>();
    xupd_kernel<<<4, 256>>>(xres, mask, gamma, out + OUT_X);

    // 7. output projection + residual
    tgemm_kernel<64, 64><<<dim3(8, 16), 256>>>(OFF_ATTN, wo, wo, wo, wo, DD,
                                               OFF_HMID, 0, h, -1, mask, NN, DD);

    // 8. FFN
    ln_kernel<<<NN, 256>>>(0, OFF_HMID, lnfw, lnfb, OFF_H2);
    tgemm_kernel<128, 128><<<dim3(32, 8), 256>>>(OFF_H2, w1, w3, w1, w1, 4 * DD,
                                                 OFF_FFA, 0, 0, -1, 0, NN, DD);
    silu_kernel<<<(NN * 4 * DD + 255) / 256, 256>>>();
    tgemm_kernel<64, 64><<<dim3(8, 16), 256>>>(OFF_FFG, w2, w2, w2, w2, DD,
                                               0, out + OUT_H, 0, OFF_HMID, mask, NN, 4 * DD);
}